// round 6
// baseline (speedup 1.0000x reference)
#include <cuda_runtime.h>
#include <cstdint>

typedef unsigned long long ull;

__constant__ float cCC[6]  = {0.f, 0.2f, 0.3f, 0.8f, (float)(8.0/9.0), 1.0f};
__constant__ float cBWv[6] = {(float)(35.0/384.0), 0.f, (float)(500.0/1113.0),
                              (float)(125.0/192.0), (float)(-2187.0/6784.0),
                              (float)(11.0/84.0)};

// ---- dynamic smem layout (bytes) ----
// [0,16)        mbar[2]
// [16, +2048)   sXs  [s:4][128] floats
// [.., +2048)   sA
// [.., +32768)  sHP  [kq:16][s:4][128] floats
// [.., +16384)  sPb  [p:2][rank:4][s:4][128] floats
// [.., +128)    sScr (32 floats)
// [.., +16)     sTx  (4)
// [.., +16)     sLp  (4)
#define SMEM_BYTES (16 + 2048 + 2048 + 32768 + 16384 + 128 + 16 + 16)

__device__ __forceinline__ ull mk2(float a, float b) {
  ull r; asm("mov.b64 %0, {%1, %2};" : "=l"(r) : "f"(a), "f"(b)); return r;
}
__device__ __forceinline__ float lo32(ull v) { return __uint_as_float((unsigned)v); }
__device__ __forceinline__ float hi32(ull v) { return __uint_as_float((unsigned)(v >> 32)); }
__device__ __forceinline__ ull f2fma(ull a, ull b, ull c) {
  ull d; asm("fma.rn.f32x2 %0,%1,%2,%3;" : "=l"(d) : "l"(a), "l"(b), "l"(c)); return d;
}
__device__ __forceinline__ ull f2mul(ull a, ull b) {
  ull d; asm("mul.rn.f32x2 %0,%1,%2;" : "=l"(d) : "l"(a), "l"(b)); return d;
}
__device__ __forceinline__ float wsum(float v) {
#pragma unroll
  for (int o = 16; o > 0; o >>= 1) v += __shfl_xor_sync(0xffffffffu, v, o);
  return v;
}
__device__ __forceinline__ uint32_t smem_u32(const void* p) {
  uint32_t a;
  asm("{.reg .u64 t; cvta.to.shared.u64 t, %1; cvt.u32.u64 %0, t;}" : "=r"(a) : "l"(p));
  return a;
}
__device__ __forceinline__ uint32_t mapa_u32(uint32_t addr, uint32_t rank) {
  uint32_t ra; asm("mapa.shared::cluster.u32 %0, %1, %2;" : "=r"(ra) : "r"(addr), "r"(rank));
  return ra;
}
__device__ __forceinline__ float ldcf(uint32_t addr, uint32_t rank) {
  uint32_t ra = mapa_u32(addr, rank);
  float v; asm volatile("ld.shared::cluster.f32 %0, [%1];" : "=f"(v) : "r"(ra)); return v;
}
__device__ __forceinline__ void csync() {
  asm volatile("barrier.cluster.arrive.aligned;" ::: "memory");
  asm volatile("barrier.cluster.wait.aligned;" ::: "memory");
}
__device__ __forceinline__ void mbar_init(uint32_t mb, unsigned cnt) {
  asm volatile("mbarrier.init.shared::cta.b64 [%0], %1;" :: "r"(mb), "r"(cnt) : "memory");
}
__device__ __forceinline__ void mbar_arm(uint32_t mb, unsigned tx) {
  asm volatile("mbarrier.arrive.expect_tx.shared::cta.b64 _, [%0], %1;"
               :: "r"(mb), "r"(tx) : "memory");
}
__device__ __forceinline__ void st_async32(uint32_t ra, float v, uint32_t rmb) {
  asm volatile("st.async.shared::cluster.mbarrier::complete_tx::bytes.b32 [%0], %1, [%2];"
               :: "r"(ra), "r"(__float_as_uint(v)), "r"(rmb) : "memory");
}
__device__ __forceinline__ void waitp(uint32_t mb, unsigned ph) {
  unsigned done;
  asm volatile(
      "{\n\t.reg .pred p;\n\t"
      "mbarrier.try_wait.parity.acquire.cluster.shared::cta.b64 p, [%1], %2;\n\t"
      "selp.u32 %0,1,0,p;\n\t}"
      : "=r"(done) : "r"(mb), "r"(ph) : "memory");
  while (!done) {
    asm volatile(
        "{\n\t.reg .pred p;\n\t"
        "mbarrier.try_wait.parity.acquire.cluster.shared::cta.b64 p, [%1], %2, 0x989680;\n\t"
        "selp.u32 %0,1,0,p;\n\t}"
        : "=r"(done) : "r"(mb), "r"(ph) : "memory");
  }
}
__device__ __forceinline__ float ftanh(float x) {
  float e = __expf(2.f * x);
  return 1.f - __fdividef(2.f, e + 1.f);
}

// GEMM tile: thread (cg = t&31, kq = t>>5) computes output cols 4cg..4cg+3
// for 4 samples over k in [8kq, 8kq+8). Weights k-pair packed: w[j][i] =
// (w_{k0}, w_{k0+1}) for col 4cg+j, k0 = 8kq+2i. x reads are warp-broadcast.
// Per-sample accumulators folded and stored immediately (low reg pressure).
__device__ __forceinline__ void gemm_t(const ull (&w)[4][4],
                                       const float* __restrict__ src,
                                       float* __restrict__ dst, int kq, int cg) {
  const float* sp = src + (kq << 3);
  float* dp = dst + (kq << 9) + (cg << 2);
#pragma unroll
  for (int s = 0; s < 4; ++s) {
    ulonglong2 xa = *(const ulonglong2*)(sp + s * 128);
    ulonglong2 xb = *(const ulonglong2*)(sp + s * 128 + 4);
    ull a0 = f2mul(w[0][0], xa.x); ull a1 = f2mul(w[1][0], xa.x);
    ull a2 = f2mul(w[2][0], xa.x); ull a3 = f2mul(w[3][0], xa.x);
    a0 = f2fma(w[0][1], xa.y, a0); a1 = f2fma(w[1][1], xa.y, a1);
    a2 = f2fma(w[2][1], xa.y, a2); a3 = f2fma(w[3][1], xa.y, a3);
    a0 = f2fma(w[0][2], xb.x, a0); a1 = f2fma(w[1][2], xb.x, a1);
    a2 = f2fma(w[2][2], xb.x, a2); a3 = f2fma(w[3][2], xb.x, a3);
    a0 = f2fma(w[0][3], xb.y, a0); a1 = f2fma(w[1][3], xb.y, a1);
    a2 = f2fma(w[2][3], xb.y, a2); a3 = f2fma(w[3][3], xb.y, a3);
    float4 r;
    r.x = lo32(a0) + hi32(a0);
    r.y = lo32(a1) + hi32(a1);
    r.z = lo32(a2) + hi32(a2);
    r.w = lo32(a3) + hi32(a3);
    *(float4*)(dp + s * 128) = r;   // contiguous across lanes: conflict-free
  }
}

__global__ void __launch_bounds__(512, 1) __cluster_dims__(4, 1, 1)
vino_kernel(const float* __restrict__ x0g, const float* __restrict__ W1g,
            const float* __restrict__ b1g, const float* __restrict__ u1g,
            const float* __restrict__ W2g, const float* __restrict__ b2g,
            const int* __restrict__ nsp, float* __restrict__ out, int B) {
  extern __shared__ __align__(16) unsigned char smraw[];
  ull*   mbar = (ull*)smraw;
  float* sXs  = (float*)(smraw + 16);
  float* sA   = sXs + 512;
  float* sHP  = sA + 512;          // 8192 floats
  float* sPb  = sHP + 8192;        // 4096 floats
  float* sScr = sPb + 4096;        // 32
  float* sTx  = sScr + 32;         // 4
  float* sLp  = sTx + 4;           // 4

  const int t = threadIdx.x;
  const int w = t >> 5, lane = t & 31;
  const int cg = t & 31, kq = t >> 5;     // GEMM tiling
  const int c = t & 127, s = t >> 7;      // epilogue element (s, c)
  uint32_t rank; asm("mov.u32 %0, %%cluster_ctarank;" : "=r"(rank));
  const int hbase = (int)rank << 7;
  const int sb = (blockIdx.x >> 2) << 2;

  // ---- persistent k-pair-packed weights: 4 cols x 4 k-pairs each GEMM ----
  ull w1p[4][4], w2p[4][4];
#pragma unroll
  for (int j = 0; j < 4; ++j)
#pragma unroll
    for (int i = 0; i < 4; ++i) {
      const int k0 = (kq << 3) + 2 * i;
      const int col = 4 * cg + j;
      w1p[j][i] = mk2(W1g[k0 * 512 + hbase + col], W1g[(k0 + 1) * 512 + hbase + col]);
      w2p[j][i] = mk2(W2g[(hbase + k0) * 128 + col], W2g[(hbase + k0 + 1) * 128 + col]);
    }

  // ---- per-element constants + state ----
  const float b1r = b1g[hbase + c];
  const float u1r = u1g[hbase + c];
  const float b2r = b2g[c];
  float mr = 0.f;
#pragma unroll 4
  for (int i = 0; i < 128; ++i)
    mr = fmaf(W1g[i * 512 + hbase + c], W2g[(hbase + c) * 128 + i], mr);
  float y = x0g[(sb + s) * 128 + c];
  float xs = y;
  sXs[s * 128 + c] = xs;

  // ---- mbarriers + remote exchange addresses ----
  const uint32_t mb0 = smem_u32(mbar);
  if (t == 0) {
    mbar_init(mb0, 1); mbar_init(mb0 + 8, 1);
    mbar_arm(mb0, 8192u); mbar_arm(mb0 + 8, 8192u);  // 4 ranks x 512 x 4B
  }
  uint32_t rdat[4], rmb[4];
  {
    const uint32_t loff = smem_u32(sPb) + (uint32_t)(((int)rank << 9) + s * 128 + c) * 4u;
#pragma unroll
    for (uint32_t r = 0; r < 4; ++r) {
      rdat[r] = mapa_u32(loff, r);
      rmb[r]  = mapa_u32(mb0, r);
    }
  }

  // ---- log p(x0) ----
  {
    float ss = wsum(y * y);
    if (lane == 0) sScr[w] = ss;
  }
  __syncthreads();
  if (t < 4) {
    float ss = sScr[4 * t] + sScr[4 * t + 1] + sScr[4 * t + 2] + sScr[4 * t + 3];
    sLp[t] = -0.5f * ss - 117.6241322501981f;  // 64*log(2*pi)
  }
  csync();  // mbar arming + smem init visible cluster-wide

  const int ns = *nsp;
  const float dt = 1.0f / (float)ns;
  float ks0 = 0.f, ks1 = 0.f, ks2 = 0.f, ks3 = 0.f, ks4 = 0.f;
  float tr = 0.f, dot = 0.f;
  unsigned par0 = 0, par1 = 0;

  for (int step = 0; step < ns; ++step) {
    const float tstep = (float)step * dt;
#pragma unroll 1
    for (int stage = 0; stage < 6; ++stage) {
      const float coef = dt * cBWv[stage];
      const float tcur = tstep + cCC[stage] * dt;
      const int p = stage & 1;

      __syncthreads();                  // S_A: sXs visible
      gemm_t(w1p, sXs, sHP, kq, cg);
      __syncthreads();                  // S_B

      // tanh + trace (one element per thread)
      {
        float h = fmaf(tcur, u1r, b1r);
#pragma unroll
        for (int q = 0; q < 16; ++q) h += sHP[(q << 9) + s * 128 + c];
        float a = ftanh(h);
        sA[s * 128 + c] = a;
        tr = fmaf((1.f - a * a) * mr, coef, tr);
      }
      __syncthreads();                  // S_C
      gemm_t(w2p, sA, sHP, kq, cg);
      __syncthreads();                  // S_D

      // fold partials, push one float to all 4 ranks
      {
        float v = 0.f;
#pragma unroll
        for (int q = 0; q < 16; ++q) v += sHP[(q << 9) + s * 128 + c];
        const uint32_t dof = (uint32_t)p << 13;   // p * 2048 floats * 4B
        const uint32_t mof = (uint32_t)p << 3;
        st_async32(rdat[0] + dof, v, rmb[0] + mof);
        st_async32(rdat[1] + dof, v, rmb[1] + mof);
        st_async32(rdat[2] + dof, v, rmb[2] + mof);
        st_async32(rdat[3] + dof, v, rmb[3] + mof);
      }

      // wait + re-arm
      {
        const uint32_t lmb = mb0 + (p << 3);
        unsigned ph = p ? par1 : par0;
        waitp(lmb, ph);
        if (p) par1 ^= 1; else par0 ^= 1;
        if (t == 0) mbar_arm(lmb, 8192u);
      }

      // assemble dxdt, dot, advance RK state (scalar, registers)
      {
        const float* pb = sPb + (p << 11) + s * 128 + c;
        float k = ((pb[0] + pb[512]) + (pb[1024] + pb[1536])) + b2r;
        dot = fmaf(xs * k, coef, dot);
        float acc;
        switch (stage) {
          case 0:
            ks0 = k;  acc = 0.2f * ks0;  break;
          case 1:
            ks1 = k;
            acc = fmaf(0.225f, ks1, 0.075f * ks0);
            break;
          case 2:
            ks2 = k;
            acc = (float)(44.0 / 45.0) * ks0;
            acc = fmaf((float)(-56.0 / 15.0), ks1, acc);
            acc = fmaf((float)(32.0 / 9.0), ks2, acc);
            break;
          case 3:
            ks3 = k;
            acc = (float)(19372.0 / 6561.0) * ks0;
            acc = fmaf((float)(-25360.0 / 2187.0), ks1, acc);
            acc = fmaf((float)(64448.0 / 6561.0), ks2, acc);
            acc = fmaf((float)(-212.0 / 729.0), ks3, acc);
            break;
          case 4:
            ks4 = k;
            acc = (float)(9017.0 / 3168.0) * ks0;
            acc = fmaf((float)(-355.0 / 33.0), ks1, acc);
            acc = fmaf((float)(46732.0 / 5247.0), ks2, acc);
            acc = fmaf((float)(49.0 / 176.0), ks3, acc);
            acc = fmaf((float)(-5103.0 / 18656.0), ks4, acc);
            break;
          default:
            acc = (float)(35.0 / 384.0) * ks0;
            acc = fmaf((float)(500.0 / 1113.0), ks2, acc);
            acc = fmaf((float)(125.0 / 192.0), ks3, acc);
            acc = fmaf((float)(-2187.0 / 6784.0), ks4, acc);
            acc = fmaf((float)(11.0 / 84.0), k, acc);
            break;
        }
        if (stage == 5) { y = fmaf(dt, acc, y); xs = y; }
        else            { xs = fmaf(dt, acc, y); }
        sXs[s * 128 + c] = xs;
      }
    }
  }

  // ---- outputs: z ----
  out[(sb + s) * 128 + c] = y;

  // ---- final reductions ----
  {
    float tw = wsum(tr), dw = wsum(dot);
    if (lane == 0) { sScr[w] = tw; sScr[16 + w] = dw; }
  }
  __syncthreads();
  if (t < 4) {
    float T = sScr[4 * t] + sScr[4 * t + 1] + sScr[4 * t + 2] + sScr[4 * t + 3];
    float D = sScr[16 + 4 * t] + sScr[17 + 4 * t] + sScr[18 + 4 * t] + sScr[19 + 4 * t];
    sTx[t] = T;
    sScr[t] = D;  // safe: reads above already done by this thread
  }
  csync();
  if (t < 4) {
    const uint32_t ta = smem_u32(&sTx[t]);
    float T4 = 0.f;
#pragma unroll
    for (uint32_t r = 0; r < 4; ++r) T4 += ldcf(ta, r);
    out[B * 128 + sb + t]     = sLp[t] - T4;   // log_px
    out[B * 128 + B + sb + t] = sScr[t] - T4;  // kl
  }
  csync();  // keep smem alive until peers finish remote reads
}

extern "C" void kernel_launch(void* const* d_in, const int* in_sizes, int n_in,
                              void* d_out, int out_size) {
  const float* x0 = (const float*)d_in[0];
  const float* W1 = (const float*)d_in[1];
  const float* b1 = (const float*)d_in[2];
  const float* u1 = (const float*)d_in[3];
  const float* W2 = (const float*)d_in[4];
  const float* b2 = (const float*)d_in[5];
  const int*   ns = (const int*)d_in[6];
  float* out = (float*)d_out;
  int B = in_sizes[0] / 128;
  cudaFuncSetAttribute(vino_kernel, cudaFuncAttributeMaxDynamicSharedMemorySize,
                       SMEM_BYTES);
  vino_kernel<<<B, 512, SMEM_BYTES>>>(x0, W1, b1, u1, W2, b2, ns, out, B);
}

// round 7
// speedup vs baseline: 1.2495x; 1.2495x over previous
#include <cuda_runtime.h>
#include <cstdint>

typedef unsigned long long ull;

__constant__ float cCC[6]  = {0.f, 0.2f, 0.3f, 0.8f, (float)(8.0/9.0), 1.0f};
__constant__ float cBWv[6] = {(float)(35.0/384.0), 0.f, (float)(500.0/1113.0),
                              (float)(125.0/192.0), (float)(-2187.0/6784.0),
                              (float)(11.0/84.0)};

// ---- smem layout (float offsets) ----
#define oXs  0        /* 512: per-sample rows [s][128] */
#define oA   512      /* 512 */
#define oHP  1024     /* 2048: [kq:4][s:4][128] GEMM partials */
#define oPb  3072     /* 4096: exchange [p:2][rank:4][pr:2][c:128] ull */
#define oStg 7168     /* 1024: staging [p:2][pr:2][c:128] ull */
#define oScr 8192     /* 32 */
#define oTx  8224     /* 4 */
#define oLp  8228     /* 4 */
#define SMF  8232

__device__ __forceinline__ ull pk(float w) {
  ull r; asm("mov.b64 %0, {%1, %2};" : "=l"(r) : "f"(w), "f"(w)); return r;
}
__device__ __forceinline__ ull mk2(float a, float b) {
  ull r; asm("mov.b64 %0, {%1, %2};" : "=l"(r) : "f"(a), "f"(b)); return r;
}
__device__ __forceinline__ float lo32(ull v) { return __uint_as_float((unsigned)v); }
__device__ __forceinline__ float hi32(ull v) { return __uint_as_float((unsigned)(v >> 32)); }
__device__ __forceinline__ ull f2fma(ull a, ull b, ull c) {
  ull d; asm("fma.rn.f32x2 %0,%1,%2,%3;" : "=l"(d) : "l"(a), "l"(b), "l"(c)); return d;
}
__device__ __forceinline__ ull f2add(ull a, ull b) {
  ull d; asm("add.rn.f32x2 %0,%1,%2;" : "=l"(d) : "l"(a), "l"(b)); return d;
}
__device__ __forceinline__ ull f2mul(ull a, ull b) {
  ull d; asm("mul.rn.f32x2 %0,%1,%2;" : "=l"(d) : "l"(a), "l"(b)); return d;
}
__device__ __forceinline__ float wsum(float v) {
#pragma unroll
  for (int o = 16; o > 0; o >>= 1) v += __shfl_xor_sync(0xffffffffu, v, o);
  return v;
}
__device__ __forceinline__ uint32_t smem_u32(const void* p) {
  uint32_t a;
  asm("{.reg .u64 t; cvta.to.shared.u64 t, %1; cvt.u32.u64 %0, t;}" : "=r"(a) : "l"(p));
  return a;
}
__device__ __forceinline__ uint32_t mapa_u32(uint32_t addr, uint32_t rank) {
  uint32_t ra; asm("mapa.shared::cluster.u32 %0, %1, %2;" : "=r"(ra) : "r"(addr), "r"(rank));
  return ra;
}
__device__ __forceinline__ float ldcf(uint32_t addr, uint32_t rank) {
  uint32_t ra = mapa_u32(addr, rank);
  float v; asm volatile("ld.shared::cluster.f32 %0, [%1];" : "=f"(v) : "r"(ra)); return v;
}
__device__ __forceinline__ void csync() {
  asm volatile("barrier.cluster.arrive.aligned;" ::: "memory");
  asm volatile("barrier.cluster.wait.aligned;" ::: "memory");
}
__device__ __forceinline__ void mbar_init(uint32_t mb, unsigned cnt) {
  asm volatile("mbarrier.init.shared::cta.b64 [%0], %1;" :: "r"(mb), "r"(cnt) : "memory");
}
__device__ __forceinline__ void mbar_arm(uint32_t mb, unsigned tx) {
  asm volatile("mbarrier.arrive.expect_tx.shared::cta.b64 _, [%0], %1;"
               :: "r"(mb), "r"(tx) : "memory");
}
// Bulk DSMEM copy: 256B warp chunk, completes on the DESTINATION CTA's mbar.
__device__ __forceinline__ void bulk_copy256(uint32_t dst_cluster, uint32_t src_cta,
                                             uint32_t rmb_cluster) {
  asm volatile(
      "cp.async.bulk.shared::cluster.shared::cta.mbarrier::complete_tx::bytes "
      "[%0], [%1], 256, [%2];"
      :: "r"(dst_cluster), "r"(src_cta), "r"(rmb_cluster) : "memory");
}
__device__ __forceinline__ void waitp(uint32_t mb, unsigned ph) {
  unsigned done;
  asm volatile(
      "{\n\t.reg .pred p;\n\t"
      "mbarrier.try_wait.parity.acquire.cluster.shared::cta.b64 p, [%1], %2;\n\t"
      "selp.u32 %0,1,0,p;\n\t}"
      : "=r"(done) : "r"(mb), "r"(ph) : "memory");
  while (!done) {
    asm volatile(
        "{\n\t.reg .pred p;\n\t"
        "mbarrier.try_wait.parity.acquire.cluster.shared::cta.b64 p, [%1], %2, 0x989680;\n\t"
        "selp.u32 %0,1,0,p;\n\t}"
        : "=r"(done) : "r"(mb), "r"(ph) : "memory");
  }
}
__device__ __forceinline__ float ftanh(float x) {
  float e = __expf(2.f * x);
  return 1.f - __fdividef(2.f, e + 1.f);
}

// GEMM quarter: thread (cq = t&63, kq = t>>6) computes output cols {cq, cq+64}
// for 4 samples over k in [32kq, 32kq+32). Weights k-pair packed. src:
// per-sample rows [s][128] (warp-broadcast reads); dst: [kq][s][128].
__device__ __forceinline__ void gemm_q(const ull (&w)[2][16],
                                       const float* __restrict__ src,
                                       float* __restrict__ dst, int kq, int cq) {
  ull a00 = 0, a01 = 0, a02 = 0, a03 = 0;   // col0, samples 0..3
  ull a10 = 0, a11 = 0, a12 = 0, a13 = 0;   // col1
  const float* s0 = src + (kq << 5);
#pragma unroll
  for (int i = 0; i < 8; ++i) {             // 4 k per iter (2 k-pairs)
    ulonglong2 x0 = *(const ulonglong2*)(s0 + 0 * 128 + (i << 2));
    ulonglong2 x1 = *(const ulonglong2*)(s0 + 1 * 128 + (i << 2));
    ulonglong2 x2 = *(const ulonglong2*)(s0 + 2 * 128 + (i << 2));
    ulonglong2 x3 = *(const ulonglong2*)(s0 + 3 * 128 + (i << 2));
    ull w0a = w[0][2 * i], w0b = w[0][2 * i + 1];
    ull w1a = w[1][2 * i], w1b = w[1][2 * i + 1];
    a00 = f2fma(w0a, x0.x, a00); a00 = f2fma(w0b, x0.y, a00);
    a01 = f2fma(w0a, x1.x, a01); a01 = f2fma(w0b, x1.y, a01);
    a02 = f2fma(w0a, x2.x, a02); a02 = f2fma(w0b, x2.y, a02);
    a03 = f2fma(w0a, x3.x, a03); a03 = f2fma(w0b, x3.y, a03);
    a10 = f2fma(w1a, x0.x, a10); a10 = f2fma(w1b, x0.y, a10);
    a11 = f2fma(w1a, x1.x, a11); a11 = f2fma(w1b, x1.y, a11);
    a12 = f2fma(w1a, x2.x, a12); a12 = f2fma(w1b, x2.y, a12);
    a13 = f2fma(w1a, x3.x, a13); a13 = f2fma(w1b, x3.y, a13);
  }
  float* d0 = dst + (kq << 9) + cq;
  d0[0 * 128]      = lo32(a00) + hi32(a00);
  d0[1 * 128]      = lo32(a01) + hi32(a01);
  d0[2 * 128]      = lo32(a02) + hi32(a02);
  d0[3 * 128]      = lo32(a03) + hi32(a03);
  d0[0 * 128 + 64] = lo32(a10) + hi32(a10);
  d0[1 * 128 + 64] = lo32(a11) + hi32(a11);
  d0[2 * 128 + 64] = lo32(a12) + hi32(a12);
  d0[3 * 128 + 64] = lo32(a13) + hi32(a13);
}

__global__ void __launch_bounds__(256, 1) __cluster_dims__(4, 1, 1)
vino_kernel(const float* __restrict__ x0g, const float* __restrict__ W1g,
            const float* __restrict__ b1g, const float* __restrict__ u1g,
            const float* __restrict__ W2g, const float* __restrict__ b2g,
            const int* __restrict__ nsp, float* __restrict__ out, int B) {
  __shared__ __align__(16) float sm[SMF];
  __shared__ __align__(8) unsigned long long smbar[2];
  const int t = threadIdx.x;
  const int w = t >> 5, lane = t & 31;
  const int cq = t & 63, kq = t >> 6;       // GEMM tiling
  const int c = t & 127, pr = t >> 7;       // epilogue: element col c, pair pr
  const int s0i = 2 * pr, s1i = 2 * pr + 1;
  const int e2 = t << 1;                    // = (pr*128 + c)*2 pair-slot floats
  uint32_t rank; asm("mov.u32 %0, %%cluster_ctarank;" : "=r"(rank));
  const int hbase = (int)rank << 7;
  const int sb = (blockIdx.x >> 2) << 2;

  // ---- persistent k-pair-packed weight registers ----
  ull w1p[2][16], w2p[2][16];
#pragma unroll
  for (int i = 0; i < 16; ++i) {
    const int kk = (kq << 5) + 2 * i;
    w1p[0][i] = mk2(W1g[kk * 512 + hbase + cq],      W1g[(kk + 1) * 512 + hbase + cq]);
    w1p[1][i] = mk2(W1g[kk * 512 + hbase + cq + 64], W1g[(kk + 1) * 512 + hbase + cq + 64]);
    w2p[0][i] = mk2(W2g[(hbase + kk) * 128 + cq],      W2g[(hbase + kk + 1) * 128 + cq]);
    w2p[1][i] = mk2(W2g[(hbase + kk) * 128 + cq + 64], W2g[(hbase + kk + 1) * 128 + cq + 64]);
  }

  // ---- per-thread constants ----
  const float b1r = b1g[hbase + c];
  const float u1r = u1g[hbase + c];
  const ull b2p = pk(b2g[c]);
  float mr = 0.f;
#pragma unroll 4
  for (int i = 0; i < 128; ++i)
    mr = fmaf(W1g[i * 512 + hbase + c], W2g[(hbase + c) * 128 + i], mr);

  // ---- state init: y holds (s0, s1) pair for element col c ----
  ull y = mk2(x0g[(sb + s0i) * 128 + c], x0g[(sb + s1i) * 128 + c]);
  ull xs = y;
  sm[oXs + s0i * 128 + c] = lo32(xs);
  sm[oXs + s1i * 128 + c] = hi32(xs);

  // ---- mbarriers + precomputed bulk-copy addresses ----
  const uint32_t mb0 = smem_u32(&smbar[0]);
  if (t == 0) {
    mbar_init(mb0, 1); mbar_init(mb0 + 8, 1);
    mbar_arm(mb0, 8192u); mbar_arm(mb0 + 8, 8192u);  // 4 ranks x 2KB
  }
  // warp chunk: 256B at byte offset w*256 within this rank's 2KB vector
  const uint32_t stgb = smem_u32(sm + oStg);
  const uint32_t spbb = smem_u32(sm + oPb);
  uint32_t dstb[4], rmb[4];
  {
    const uint32_t doff = spbb + ((uint32_t)rank << 11) + ((uint32_t)w << 8);
#pragma unroll
    for (uint32_t r = 0; r < 4; ++r) {
      dstb[r] = mapa_u32(doff, r);
      rmb[r]  = mapa_u32(mb0, r);
    }
  }

  // ---- log p(x0) ----
  {
    float q0 = lo32(y), q1 = hi32(y);
    float ss0 = wsum(q0 * q0), ss1 = wsum(q1 * q1);
    if (lane == 0) { sm[oScr + w * 2] = ss0; sm[oScr + w * 2 + 1] = ss1; }
  }
  __syncthreads();
  if (t < 4) {
    const int gg = t >> 1, sp = t & 1;
    float ss = 0.f;
#pragma unroll
    for (int q = 0; q < 4; ++q) ss += sm[oScr + ((4 * gg + q) << 1) + sp];
    sm[oLp + t] = -0.5f * ss - 117.6241322501981f;  // 64*log(2*pi)
  }
  csync();  // mbar arming + smem init visible cluster-wide

  const int ns = *nsp;
  const float dt = 1.0f / (float)ns;
  ull ks0 = 0, ks1 = 0, ks2 = 0, ks3 = 0, ks4 = 0;
  float tr0 = 0.f, tr1 = 0.f;
  ull acc_dot = 0;
  unsigned par0 = 0, par1 = 0;

  for (int step = 0; step < ns; ++step) {
    const float tstep = (float)step * dt;
#pragma unroll 1
    for (int stage = 0; stage < 6; ++stage) {
      const float coef = dt * cBWv[stage];
      const float tcur = tstep + cCC[stage] * dt;
      const int p = stage & 1;

      __syncthreads();                       // S_A: oXs visible
      gemm_q(w1p, sm + oXs, sm + oHP, kq, cq);
      __syncthreads();                       // S_B

      // tanh + trace accumulation (element (c, s0/s1))
      {
        const float bias = fmaf(tcur, u1r, b1r);
        float h0 = (sm[oHP + s0i * 128 + c]        + sm[oHP + 512 + s0i * 128 + c]) +
                   (sm[oHP + 1024 + s0i * 128 + c] + sm[oHP + 1536 + s0i * 128 + c]) + bias;
        float h1 = (sm[oHP + s1i * 128 + c]        + sm[oHP + 512 + s1i * 128 + c]) +
                   (sm[oHP + 1024 + s1i * 128 + c] + sm[oHP + 1536 + s1i * 128 + c]) + bias;
        float a0 = ftanh(h0), a1 = ftanh(h1);
        sm[oA + s0i * 128 + c] = a0;
        sm[oA + s1i * 128 + c] = a1;
        tr0 = fmaf((1.f - a0 * a0) * mr, coef, tr0);
        tr1 = fmaf((1.f - a1 * a1) * mr, coef, tr1);
      }
      __syncthreads();                       // S_C
      gemm_q(w2p, sm + oA, sm + oHP, kq, cq);
      __syncthreads();                       // S_D

      // fold 4 k-quarters into parity staging, warp-local; lane 0 bulk-pushes
      // the warp's 256B chunk to all 4 ranks.
      {
        float v0 = (sm[oHP + s0i * 128 + c]        + sm[oHP + 512 + s0i * 128 + c]) +
                   (sm[oHP + 1024 + s0i * 128 + c] + sm[oHP + 1536 + s0i * 128 + c]);
        float v1 = (sm[oHP + s1i * 128 + c]        + sm[oHP + 512 + s1i * 128 + c]) +
                   (sm[oHP + 1024 + s1i * 128 + c] + sm[oHP + 1536 + s1i * 128 + c]);
        ((ull*)(sm + oStg))[(p << 8) + pr * 128 + c] = mk2(v0, v1);
        __syncwarp();
        if (lane == 0) {
          asm volatile("fence.proxy.async.shared::cta;" ::: "memory");
          const uint32_t src = stgb + ((uint32_t)p << 11) + ((uint32_t)w << 8);
          const uint32_t dof = (uint32_t)p << 13;   // p * 8192 B
          const uint32_t mof = (uint32_t)p << 3;
          bulk_copy256(dstb[0] + dof, src, rmb[0] + mof);
          bulk_copy256(dstb[1] + dof, src, rmb[1] + mof);
          bulk_copy256(dstb[2] + dof, src, rmb[2] + mof);
          bulk_copy256(dstb[3] + dof, src, rmb[3] + mof);
        }
      }

      // wait for all 8KB of this buffer, re-arm for its next use
      {
        const uint32_t lmb = mb0 + (p << 3);
        unsigned ph = p ? par1 : par0;
        waitp(lmb, ph);
        if (p) par1 ^= 1; else par0 ^= 1;
        if (t == 0) mbar_arm(lmb, 8192u);
      }

      // assemble dxdt, accumulate dot, advance RK state (registers)
      {
        const float* pb = sm + oPb + (p << 11);
        ull kacc = f2add(f2add(*(const ull*)(pb + e2),        *(const ull*)(pb + 512 + e2)),
                         f2add(*(const ull*)(pb + 1024 + e2), *(const ull*)(pb + 1536 + e2)));
        kacc = f2add(kacc, b2p);
        acc_dot = f2fma(f2mul(xs, kacc), pk(coef), acc_dot);
        ull acc;
        switch (stage) {
          case 0:
            ks0 = kacc;
            acc = f2mul(pk(0.2f), ks0);
            xs = f2fma(pk(dt), acc, y);
            break;
          case 1:
            ks1 = kacc;
            acc = f2mul(pk(0.075f), ks0);
            acc = f2fma(pk(0.225f), ks1, acc);
            xs = f2fma(pk(dt), acc, y);
            break;
          case 2:
            ks2 = kacc;
            acc = f2mul(pk((float)(44.0 / 45.0)), ks0);
            acc = f2fma(pk((float)(-56.0 / 15.0)), ks1, acc);
            acc = f2fma(pk((float)(32.0 / 9.0)), ks2, acc);
            xs = f2fma(pk(dt), acc, y);
            break;
          case 3:
            ks3 = kacc;
            acc = f2mul(pk((float)(19372.0 / 6561.0)), ks0);
            acc = f2fma(pk((float)(-25360.0 / 2187.0)), ks1, acc);
            acc = f2fma(pk((float)(64448.0 / 6561.0)), ks2, acc);
            acc = f2fma(pk((float)(-212.0 / 729.0)), ks3, acc);
            xs = f2fma(pk(dt), acc, y);
            break;
          case 4:
            ks4 = kacc;
            acc = f2mul(pk((float)(9017.0 / 3168.0)), ks0);
            acc = f2fma(pk((float)(-355.0 / 33.0)), ks1, acc);
            acc = f2fma(pk((float)(46732.0 / 5247.0)), ks2, acc);
            acc = f2fma(pk((float)(49.0 / 176.0)), ks3, acc);
            acc = f2fma(pk((float)(-5103.0 / 18656.0)), ks4, acc);
            xs = f2fma(pk(dt), acc, y);
            break;
          default:
            acc = f2mul(pk((float)(35.0 / 384.0)), ks0);
            acc = f2fma(pk((float)(500.0 / 1113.0)), ks2, acc);
            acc = f2fma(pk((float)(125.0 / 192.0)), ks3, acc);
            acc = f2fma(pk((float)(-2187.0 / 6784.0)), ks4, acc);
            acc = f2fma(pk((float)(11.0 / 84.0)), kacc, acc);
            y = f2fma(pk(dt), acc, y);
            xs = y;
            break;
        }
        sm[oXs + s0i * 128 + c] = lo32(xs);
        sm[oXs + s1i * 128 + c] = hi32(xs);
      }
    }
  }

  // ---- outputs: z ----
  out[(sb + s0i) * 128 + c] = lo32(y);
  out[(sb + s1i) * 128 + c] = hi32(y);

  // ---- final reductions: trace (cross-CTA) and dot (local) ----
  {
    float tlo = wsum(tr0), thi = wsum(tr1);
    float dlo = wsum(lo32(acc_dot)), dhi = wsum(hi32(acc_dot));
    if (lane == 0) {
      sm[oScr + w * 4 + 0] = tlo; sm[oScr + w * 4 + 1] = thi;
      sm[oScr + w * 4 + 2] = dlo; sm[oScr + w * 4 + 3] = dhi;
    }
  }
  __syncthreads();
  if (t < 4) {
    const int gg = t >> 1, sp = t & 1;
    float T = 0.f, D = 0.f;
#pragma unroll
    for (int q = 0; q < 4; ++q) {
      T += sm[oScr + (4 * gg + q) * 4 + sp];
      D += sm[oScr + (4 * gg + q) * 4 + 2 + sp];
    }
    sm[oTx + t] = T;
    sm[oScr + t] = D;  // reuse scratch (post-sync)
  }
  csync();
  if (t < 4) {
    const uint32_t ta = smem_u32(&sm[oTx + t]);
    float T4 = 0.f;
#pragma unroll
    for (uint32_t r = 0; r < 4; ++r) T4 += ldcf(ta, r);
    out[B * 128 + sb + t]     = sm[oLp + t] - T4;       // log_px
    out[B * 128 + B + sb + t] = sm[oScr + t] - T4;      // kl
  }
  csync();  // keep smem alive until peers finish remote reads
}

extern "C" void kernel_launch(void* const* d_in, const int* in_sizes, int n_in,
                              void* d_out, int out_size) {
  const float* x0 = (const float*)d_in[0];
  const float* W1 = (const float*)d_in[1];
  const float* b1 = (const float*)d_in[2];
  const float* u1 = (const float*)d_in[3];
  const float* W2 = (const float*)d_in[4];
  const float* b2 = (const float*)d_in[5];
  const int*   ns = (const int*)d_in[6];
  float* out = (float*)d_out;
  int B = in_sizes[0] / 128;
  vino_kernel<<<B, 256>>>(x0, W1, b1, u1, W2, b2, ns, out, B);
}